// round 7
// baseline (speedup 1.0000x reference)
#include <cuda_runtime.h>
#include <cuda_bf16.h>
#include <cstdint>

#define NA      100000
#define NM      12
#define NROWS   (NA*NM)          // 1,200,000
#define OUTC    128
#define ATOMF   64
#define EDGEF   41
#define INF     169
#define PAD     132              // padded row stride (floats) for transposed tiles

// ---------------- device scratch (allocation-free: __device__ globals) ----------------
__device__ float  g_P [(size_t)NA*128];          // self projection  [n][slot]
__device__ float  g_Pn[(size_t)NA*128];          // nbr  projection  [n][slot]
__device__ float  g_gated[(size_t)NROWS*128];    // gated pre-BN     [row][slot] (614.4 MB)
__device__ float  g_s[(size_t)NA*64];            // nbr_sumed pre-BN2
__device__ double g_sum1[128], g_sq1[128];
__device__ double g_sum2[64],  g_sq2[64];
__device__ float  g_scale1p[128], g_shift1p[128];  // BN1 affine, permuted (slot) layout
__device__ float  g_scale2[64],   g_shift2[64];    // BN2 affine, plain layout

// ---------------- helpers ----------------
__device__ __forceinline__ unsigned long long pk(float lo, float hi) {
    unsigned long long r;
    asm("mov.b64 %0, {%1,%2};" : "=l"(r) : "f"(lo), "f"(hi));
    return r;
}
__device__ __forceinline__ float2 upk(unsigned long long v) {
    float lo, hi;
    asm("mov.b64 {%0,%1}, %2;" : "=f"(lo), "=f"(hi) : "l"(v));
    return make_float2(lo, hi);
}
// packed fp32x2 fma: d = a*b + d  (FFMA2 -> 2x fp32 FMA throughput on sm_103a)
__device__ __forceinline__ void ffma2(unsigned long long& d,
                                      unsigned long long a, unsigned long long b) {
    asm("fma.rn.f32x2 %0, %1, %2, %0;" : "+l"(d) : "l"(a), "l"(b));
}
__device__ __forceinline__ float softplusf(float x) {
    return fmaxf(x, 0.f) + log1pf(__expf(-fabsf(x)));
}
__device__ __forceinline__ float sigmoidf_(float x) {
    return 1.f / (1.f + __expf(-x));
}

// ---------------- K0: zero stat accumulators (must run every graph replay) ----------------
__global__ void k0_zero() {
    int t = threadIdx.x;
    if (t < 128) { g_sum1[t] = 0.0; g_sq1[t] = 0.0; }
    if (t < 64)  { g_sum2[t] = 0.0; g_sq2[t] = 0.0; }
}

// ---------------- K1: per-atom projections P_self / P_nbr ----------------
// tile: 128 atoms x 128 outputs. blockIdx.y: 0 -> self (W cols 0..63), 1 -> nbr (64..127)
// thread (tc=tid&31, tr=tid>>5): 16 rows (8 f32x2 row-pairs) x 4 outputs (o = tc+32j).
// store permuted: dst[n*128 + tc*4 + j]   (slot = (o%32)*4 + o/32)
#define SMEM_K1 (64*128*8 + 64*PAD*4)
__global__ __launch_bounds__(256) void k1_proj(const float* __restrict__ atom,
                                               const float* __restrict__ fcw) {
    extern __shared__ unsigned long long sm_u64[];
    unsigned long long* W2 = sm_u64;                 // [64][128] splat-packed
    float* At = (float*)(W2 + 64*128);               // [64][PAD] transposed A tile
    const int tid = threadIdx.x;
    const int tc = tid & 31, tr = tid >> 5;
    const int wbase = blockIdx.y ? 64 : 0;
    const long rowbase = (long)blockIdx.x * 128;

    for (int i = tid; i < 64*128; i += 256) {
        int o = i >> 6, f = i & 63;
        float w = fcw[o*INF + wbase + f];
        W2[f*128 + o] = pk(w, w);
    }
    for (int i = tid; i < 128*64; i += 256) {
        int r = i >> 6, f = i & 63;
        long gr = rowbase + r;
        At[f*PAD + r] = (gr < NA) ? atom[gr*64 + f] : 0.f;
    }
    __syncthreads();

    unsigned long long acc[8][4];
#pragma unroll
    for (int rp = 0; rp < 8; rp++)
#pragma unroll
        for (int j = 0; j < 4; j++) acc[rp][j] = 0ull;

    const int myrow0 = tr * 16;
#pragma unroll 2
    for (int f = 0; f < 64; f++) {
        const unsigned long long* wrow = W2 + f*128;
        unsigned long long w[4];
#pragma unroll
        for (int j = 0; j < 4; j++) w[j] = wrow[tc + 32*j];
        const ulonglong2* av = (const ulonglong2*)(At + f*PAD + myrow0);
#pragma unroll
        for (int q = 0; q < 4; q++) {
            ulonglong2 a = av[q];
#pragma unroll
            for (int j = 0; j < 4; j++) {
                ffma2(acc[2*q  ][j], a.x, w[j]);
                ffma2(acc[2*q+1][j], a.y, w[j]);
            }
        }
    }

    float* dst = blockIdx.y ? g_Pn : g_P;
#pragma unroll
    for (int rp = 0; rp < 8; rp++) {
        long r0 = rowbase + myrow0 + 2*rp;
        long r1 = r0 + 1;
        float2 v0 = upk(acc[rp][0]), v1 = upk(acc[rp][1]);
        float2 v2 = upk(acc[rp][2]), v3 = upk(acc[rp][3]);
        if (r0 < NA) *(float4*)(dst + r0*128 + tc*4) = make_float4(v0.x, v1.x, v2.x, v3.x);
        if (r1 < NA) *(float4*)(dst + r1*128 + tc*4) = make_float4(v0.y, v1.y, v2.y, v3.y);
    }
}

// ---------------- K2: edge GEMM + gather + gated store + BN1 stats ----------------
// tile: 128 edge-rows x 128 outputs.
// gated[row][o] = P_self[n][o] + P_nbr[k][o] + E[row] @ W_edge[o]   (fc_b cancels under BN)
#define SMEM_K2 (41*128*8 + 41*PAD*4 + 8*128*4*2 + 128*4*2)
__global__ __launch_bounds__(256) void k2_gated(const float* __restrict__ nbr,
                                                const int* __restrict__ idxv,
                                                const float* __restrict__ fcw) {
    extern __shared__ unsigned long long sm_u64[];
    unsigned long long* W2 = sm_u64;                 // [41][128] splat-packed
    float* Et   = (float*)(W2 + 41*128);             // [41][PAD] transposed E tile
    float* sSum = Et + 41*PAD;                       // [8][128]
    float* sSq  = sSum + 8*128;                      // [8][128]
    int*   sK   = (int*)(sSq + 8*128);               // [128]
    int*   sN   = sK + 128;                          // [128]
    const int tid = threadIdx.x;
    const int tc = tid & 31, tr = tid >> 5;
    const long rowbase = (long)blockIdx.x * 128;

    for (int i = tid; i < 41*128; i += 256) {
        int o = i / 41, e = i - o*41;
        float w = fcw[o*INF + 128 + e];
        W2[e*128 + o] = pk(w, w);
    }
    for (int i = tid; i < 128*41; i += 256) {
        int r = i / 41, e = i - r*41;
        Et[e*PAD + r] = nbr[rowbase*41 + i];
    }
    if (tid < 128) {
        sK[tid] = idxv[rowbase + tid];
        sN[tid] = (int)((rowbase + tid) / 12);
    }
    __syncthreads();

    const int myrow0 = tr * 16;
    unsigned long long acc[8][4];
#pragma unroll
    for (int rp = 0; rp < 8; rp++) {
        int r0 = myrow0 + 2*rp, r1 = r0 + 1;
        float4 s0 = *(const float4*)(g_P  + (long)sN[r0]*128 + tc*4);
        float4 q0 = *(const float4*)(g_Pn + (long)sK[r0]*128 + tc*4);
        float4 s1 = *(const float4*)(g_P  + (long)sN[r1]*128 + tc*4);
        float4 q1 = *(const float4*)(g_Pn + (long)sK[r1]*128 + tc*4);
        acc[rp][0] = pk(s0.x + q0.x, s1.x + q1.x);
        acc[rp][1] = pk(s0.y + q0.y, s1.y + q1.y);
        acc[rp][2] = pk(s0.z + q0.z, s1.z + q1.z);
        acc[rp][3] = pk(s0.w + q0.w, s1.w + q1.w);
    }

#pragma unroll 2
    for (int e = 0; e < 41; e++) {
        const unsigned long long* wrow = W2 + e*128;
        unsigned long long w[4];
#pragma unroll
        for (int j = 0; j < 4; j++) w[j] = wrow[tc + 32*j];
        const ulonglong2* av = (const ulonglong2*)(Et + e*PAD + myrow0);
#pragma unroll
        for (int q = 0; q < 4; q++) {
            ulonglong2 a = av[q];
#pragma unroll
            for (int j = 0; j < 4; j++) {
                ffma2(acc[2*q  ][j], a.x, w[j]);
                ffma2(acc[2*q+1][j], a.y, w[j]);
            }
        }
    }

    float ps[4] = {0,0,0,0}, pq[4] = {0,0,0,0};
#pragma unroll
    for (int rp = 0; rp < 8; rp++) {
        long r0 = rowbase + myrow0 + 2*rp, r1 = r0 + 1;
        float2 v0 = upk(acc[rp][0]), v1 = upk(acc[rp][1]);
        float2 v2 = upk(acc[rp][2]), v3 = upk(acc[rp][3]);
        *(float4*)(g_gated + r0*128 + tc*4) = make_float4(v0.x, v1.x, v2.x, v3.x);
        *(float4*)(g_gated + r1*128 + tc*4) = make_float4(v0.y, v1.y, v2.y, v3.y);
        ps[0] += v0.x + v0.y;  pq[0] += v0.x*v0.x + v0.y*v0.y;
        ps[1] += v1.x + v1.y;  pq[1] += v1.x*v1.x + v1.y*v1.y;
        ps[2] += v2.x + v2.y;  pq[2] += v2.x*v2.x + v2.y*v2.y;
        ps[3] += v3.x + v3.y;  pq[3] += v3.x*v3.x + v3.y*v3.y;
    }
#pragma unroll
    for (int j = 0; j < 4; j++) {
        int o = tc + 32*j;                 // true channel index
        sSum[tr*128 + o] = ps[j];
        sSq [tr*128 + o] = pq[j];
    }
    __syncthreads();
    if (tid < 128) {
        float s = 0.f, q = 0.f;
#pragma unroll
        for (int t = 0; t < 8; t++) { s += sSum[t*128 + tid]; q += sSq[t*128 + tid]; }
        atomicAdd(&g_sum1[tid], (double)s);
        atomicAdd(&g_sq1 [tid], (double)q);
    }
}

// ---------------- K3a: finalize BN1 affine (permuted layout) ----------------
__global__ void k3_bn1(const float* __restrict__ gam, const float* __restrict__ bet) {
    int o = threadIdx.x;                   // 128 threads
    double mean = g_sum1[o] / (double)NROWS;
    double var  = g_sq1[o] / (double)NROWS - mean * mean;
    float scale = gam[o] * rsqrtf((float)var + 1e-5f);
    float shift = bet[o] - (float)mean * scale;
    int s = (o & 31) * 4 + (o >> 5);
    g_scale1p[s] = scale;
    g_shift1p[s] = shift;
}

// ---------------- K4: BN1 affine + sigmoid*softplus + sum over M + BN2 stats ----------------
__global__ __launch_bounds__(256) void k4_reduce() {
    __shared__ double sS[64], sQ[64];
    int tid = threadIdx.x;
    if (tid < 64) { sS[tid] = 0.0; sQ[tid] = 0.0; }
    __syncthreads();
    int l = tid & 31, w = tid >> 5;
    long n = (long)blockIdx.x * 8 + w;
    float4 sc = *(const float4*)(g_scale1p + l*4);
    float4 sh = *(const float4*)(g_shift1p + l*4);
    float s0 = 0.f, s1 = 0.f;
    long base = n * 12 * 128 + l * 4;
#pragma unroll
    for (int m = 0; m < 12; m++) {
        float4 v = *(const float4*)(g_gated + base + (long)m*128);
        float a0 = fmaf(v.x, sc.x, sh.x);
        float a1 = fmaf(v.y, sc.y, sh.y);
        float a2 = fmaf(v.z, sc.z, sh.z);
        float a3 = fmaf(v.w, sc.w, sh.w);
        s0 += sigmoidf_(a0) * softplusf(a2);
        s1 += sigmoidf_(a1) * softplusf(a3);
    }
    g_s[n*64 + l]      = s0;
    g_s[n*64 + 32 + l] = s1;
    atomicAdd(&sS[l],      (double)s0);
    atomicAdd(&sQ[l],      (double)s0 * (double)s0);
    atomicAdd(&sS[l + 32], (double)s1);
    atomicAdd(&sQ[l + 32], (double)s1 * (double)s1);
    __syncthreads();
    if (tid < 64) {
        atomicAdd(&g_sum2[tid], sS[tid]);
        atomicAdd(&g_sq2 [tid], sQ[tid]);
    }
}

// ---------------- K3b: finalize BN2 affine ----------------
__global__ void k3_bn2(const float* __restrict__ gam, const float* __restrict__ bet) {
    int c = threadIdx.x;                   // 64 threads
    double mean = g_sum2[c] / (double)NA;
    double var  = g_sq2[c] / (double)NA - mean * mean;
    float scale = gam[c] * rsqrtf((float)var + 1e-5f);
    g_scale2[c] = scale;
    g_shift2[c] = bet[c] - (float)mean * scale;
}

// ---------------- K5: out = softplus(atom + BN2(nbr_sumed)) ----------------
__global__ __launch_bounds__(256) void k5_out(const float* __restrict__ atom,
                                              float* __restrict__ out) {
    int i = blockIdx.x * 256 + threadIdx.x;     // one float4 group per thread
    int c4 = (i & 15) * 4;
    float4 a  = ((const float4*)atom)[i];
    float4 sv = ((const float4*)g_s)[i];
    float4 sc = *(const float4*)(g_scale2 + c4);
    float4 sh = *(const float4*)(g_shift2 + c4);
    float4 r;
    r.x = softplusf(a.x + fmaf(sv.x, sc.x, sh.x));
    r.y = softplusf(a.y + fmaf(sv.y, sc.y, sh.y));
    r.z = softplusf(a.z + fmaf(sv.z, sc.z, sh.z));
    r.w = softplusf(a.w + fmaf(sv.w, sc.w, sh.w));
    ((float4*)out)[i] = r;
}

// ---------------- launch ----------------
extern "C" void kernel_launch(void* const* d_in, const int* in_sizes, int n_in,
                              void* d_out, int out_size) {
    const float* atom = (const float*)d_in[0];   // [100000,64]
    const float* nbr  = (const float*)d_in[1];   // [100000,12,41]
    const int*   idxv = (const int*)  d_in[2];   // [100000,12]
    const float* fcw  = (const float*)d_in[3];   // [128,169]
    // d_in[4] = fc_b : cancels under BN1, unused
    const float* g1   = (const float*)d_in[5];
    const float* b1   = (const float*)d_in[6];
    const float* g2   = (const float*)d_in[7];
    const float* b2   = (const float*)d_in[8];
    float* out = (float*)d_out;

    cudaFuncSetAttribute(k1_proj,  cudaFuncAttributeMaxDynamicSharedMemorySize, SMEM_K1);
    cudaFuncSetAttribute(k2_gated, cudaFuncAttributeMaxDynamicSharedMemorySize, SMEM_K2);

    k0_zero<<<1, 128>>>();
    dim3 gk1((NA + 127) / 128, 2);
    k1_proj <<<gk1, 256, SMEM_K1>>>(atom, fcw);
    k2_gated<<<NROWS / 128, 256, SMEM_K2>>>(nbr, idxv, fcw);
    k3_bn1  <<<1, 128>>>(g1, b1);
    k4_reduce<<<NA / 8, 256>>>();
    k3_bn2  <<<1, 64>>>(g2, b2);
    k5_out  <<<(NA * 64 / 4) / 256, 256>>>(atom, out);
}

// round 10
// speedup vs baseline: 1.5590x; 1.5590x over previous
#include <cuda_runtime.h>
#include <cuda_fp16.h>
#include <cstdint>

#define NA      100000
#define NM      12
#define NROWS   (NA*NM)          // 1,200,000
#define OUTC    128
#define ATOMF   64
#define EDGEF   41
#define INF     169
#define PAD     132              // padded row stride (floats) for transposed tiles

// ---------------- device scratch (allocation-free: __device__ globals) ----------------
__device__ __half  g_P [(size_t)NA*128];         // self projection  [n][slot]  fp16 (25.6MB)
__device__ __half  g_Pn[(size_t)NA*128];         // nbr  projection  [n][slot]  fp16 (25.6MB)
__device__ __half  g_gated[(size_t)NROWS*128];   // gated pre-BN     [row][slot] fp16 (307MB)
__device__ float   g_s[(size_t)NA*64];           // nbr_sumed pre-BN2
__device__ double  g_sum1[128], g_sq1[128];
__device__ double  g_sum2[64],  g_sq2[64];

// ---------------- helpers ----------------
__device__ __forceinline__ unsigned long long pk(float lo, float hi) {
    unsigned long long r;
    asm("mov.b64 %0, {%1,%2};" : "=l"(r) : "f"(lo), "f"(hi));
    return r;
}
__device__ __forceinline__ float2 upk(unsigned long long v) {
    float lo, hi;
    asm("mov.b64 {%0,%1}, %2;" : "=f"(lo), "=f"(hi) : "l"(v));
    return make_float2(lo, hi);
}
// packed fp32x2 fma: d = a*b + d  (FFMA2 -> 2x fp32 FMA throughput on sm_103a)
__device__ __forceinline__ void ffma2(unsigned long long& d,
                                      unsigned long long a, unsigned long long b) {
    asm("fma.rn.f32x2 %0, %1, %2, %0;" : "+l"(d) : "l"(a), "l"(b));
}
// pack two fp32 into fp16x2 (lo = a, hi = b) — single F2FP.PACK
__device__ __forceinline__ unsigned int packh2(float a, float b) {
    unsigned int r;
    asm("cvt.rn.f16x2.f32 %0, %2, %1;" : "=r"(r) : "f"(a), "f"(b));
    return r;
}
__device__ __forceinline__ float2 unph2(unsigned int u) {
    __half2 h = *(__half2*)&u;
    return __half22float2(h);
}
__device__ __forceinline__ float softplusf(float x) {
    return fmaxf(x, 0.f) + __logf(1.f + __expf(-fabsf(x)));
}
__device__ __forceinline__ float sigmoidf_(float x) {
    return 1.f / (1.f + __expf(-x));
}

// ---------------- K0: zero stat accumulators (must run every graph replay) ----------------
__global__ void k0_zero() {
    int t = threadIdx.x;
    if (t < 128) { g_sum1[t] = 0.0; g_sq1[t] = 0.0; }
    if (t < 64)  { g_sum2[t] = 0.0; g_sq2[t] = 0.0; }
}

// ---------------- K1: per-atom projections P_self / P_nbr (fp16 output) ----------------
// tile: 128 atoms x 128 outputs. blockIdx.y: 0 -> self (W cols 0..63), 1 -> nbr (64..127)
// thread (tc=lane, tr=warp): 16 rows (8 f32x2 row-pairs) x 4 outputs (o = tc+32j).
// store permuted: dst[n*128 + tc*4 + j]   (slot = (o%32)*4 + o/32)
#define SMEM_K1 (64*128*8 + 64*PAD*4)
__global__ __launch_bounds__(256) void k1_proj(const float* __restrict__ atom,
                                               const float* __restrict__ fcw) {
    extern __shared__ unsigned long long sm_u64[];
    unsigned long long* W2 = sm_u64;                 // [64][128] splat-packed
    float* At = (float*)(W2 + 64*128);               // [64][PAD] transposed A tile
    const int tid = threadIdx.x;
    const int tc = tid & 31, tr = tid >> 5;
    const int wbase = blockIdx.y ? 64 : 0;
    const long rowbase = (long)blockIdx.x * 128;

    for (int i = tid; i < 64*128; i += 256) {
        int o = i >> 6, f = i & 63;
        float w = fcw[o*INF + wbase + f];
        W2[f*128 + o] = pk(w, w);
    }
    for (int i = tid; i < 128*64; i += 256) {
        int r = i >> 6, f = i & 63;
        long gr = rowbase + r;
        At[f*PAD + r] = (gr < NA) ? atom[gr*64 + f] : 0.f;
    }
    __syncthreads();

    unsigned long long acc[8][4];
#pragma unroll
    for (int rp = 0; rp < 8; rp++)
#pragma unroll
        for (int j = 0; j < 4; j++) acc[rp][j] = 0ull;

    const int myrow0 = tr * 16;
#pragma unroll 2
    for (int f = 0; f < 64; f++) {
        const unsigned long long* wrow = W2 + f*128;
        unsigned long long w[4];
#pragma unroll
        for (int j = 0; j < 4; j++) w[j] = wrow[tc + 32*j];
        const ulonglong2* av = (const ulonglong2*)(At + f*PAD + myrow0);
#pragma unroll
        for (int q = 0; q < 4; q++) {
            ulonglong2 a = av[q];
#pragma unroll
            for (int j = 0; j < 4; j++) {
                ffma2(acc[2*q  ][j], a.x, w[j]);
                ffma2(acc[2*q+1][j], a.y, w[j]);
            }
        }
    }

    __half* dst = blockIdx.y ? g_Pn : g_P;
#pragma unroll
    for (int rp = 0; rp < 8; rp++) {
        long r0 = rowbase + myrow0 + 2*rp;
        long r1 = r0 + 1;
        float2 v0 = upk(acc[rp][0]), v1 = upk(acc[rp][1]);
        float2 v2 = upk(acc[rp][2]), v3 = upk(acc[rp][3]);
        if (r0 < NA) {
            uint2 s; s.x = packh2(v0.x, v1.x); s.y = packh2(v2.x, v3.x);
            *(uint2*)(dst + r0*128 + tc*4) = s;
        }
        if (r1 < NA) {
            uint2 s; s.x = packh2(v0.y, v1.y); s.y = packh2(v2.y, v3.y);
            *(uint2*)(dst + r1*128 + tc*4) = s;
        }
    }
}

// ---------------- K2: edge GEMM + gather + gated store (fp16) + BN1 stats ----------------
// gated[row][o] = P_self[n][o] + P_nbr[k][o] + E[row] @ W_edge[o]   (fc_b cancels under BN)
#define SMEM_K2 (41*128*8 + 41*PAD*4 + 8*128*4*2 + 128*4*2)
__global__ __launch_bounds__(256) void k2_gated(const float* __restrict__ nbr,
                                                const int* __restrict__ idxv,
                                                const float* __restrict__ fcw) {
    extern __shared__ unsigned long long sm_u64[];
    unsigned long long* W2 = sm_u64;                 // [41][128] splat-packed
    float* Et   = (float*)(W2 + 41*128);             // [41][PAD] transposed E tile
    float* sSum = Et + 41*PAD;                       // [8][128]
    float* sSq  = sSum + 8*128;                      // [8][128]
    int*   sK   = (int*)(sSq + 8*128);               // [128]
    int*   sN   = sK + 128;                          // [128]
    const int tid = threadIdx.x;
    const int tc = tid & 31, tr = tid >> 5;
    const long rowbase = (long)blockIdx.x * 128;

    for (int i = tid; i < 41*128; i += 256) {
        int o = i / 41, e = i - o*41;
        float w = fcw[o*INF + 128 + e];
        W2[e*128 + o] = pk(w, w);
    }
    for (int i = tid; i < 128*41; i += 256) {
        int r = i / 41, e = i - r*41;
        Et[e*PAD + r] = nbr[rowbase*41 + i];
    }
    if (tid < 128) {
        sK[tid] = idxv[rowbase + tid];
        sN[tid] = (int)((rowbase + tid) / 12);
    }
    __syncthreads();

    const int myrow0 = tr * 16;
    unsigned long long acc[8][4];
#pragma unroll
    for (int rp = 0; rp < 8; rp++) {
        int r0 = myrow0 + 2*rp, r1 = r0 + 1;
        uint2 us0 = *(const uint2*)(g_P  + (size_t)sN[r0]*128 + tc*4);
        uint2 uq0 = *(const uint2*)(g_Pn + (size_t)sK[r0]*128 + tc*4);
        uint2 us1 = *(const uint2*)(g_P  + (size_t)sN[r1]*128 + tc*4);
        uint2 uq1 = *(const uint2*)(g_Pn + (size_t)sK[r1]*128 + tc*4);
        float2 sA0 = unph2(us0.x), sB0 = unph2(us0.y);
        float2 qA0 = unph2(uq0.x), qB0 = unph2(uq0.y);
        float2 sA1 = unph2(us1.x), sB1 = unph2(us1.y);
        float2 qA1 = unph2(uq1.x), qB1 = unph2(uq1.y);
        acc[rp][0] = pk(sA0.x + qA0.x, sA1.x + qA1.x);
        acc[rp][1] = pk(sA0.y + qA0.y, sA1.y + qA1.y);
        acc[rp][2] = pk(sB0.x + qB0.x, sB1.x + qB1.x);
        acc[rp][3] = pk(sB0.y + qB0.y, sB1.y + qB1.y);
    }

#pragma unroll 2
    for (int e = 0; e < 41; e++) {
        const unsigned long long* wrow = W2 + e*128;
        unsigned long long w[4];
#pragma unroll
        for (int j = 0; j < 4; j++) w[j] = wrow[tc + 32*j];
        const ulonglong2* av = (const ulonglong2*)(Et + e*PAD + myrow0);
#pragma unroll
        for (int q = 0; q < 4; q++) {
            ulonglong2 a = av[q];
#pragma unroll
            for (int j = 0; j < 4; j++) {
                ffma2(acc[2*q  ][j], a.x, w[j]);
                ffma2(acc[2*q+1][j], a.y, w[j]);
            }
        }
    }

    float ps[4] = {0,0,0,0}, pq[4] = {0,0,0,0};
#pragma unroll
    for (int rp = 0; rp < 8; rp++) {
        long r0 = rowbase + myrow0 + 2*rp, r1 = r0 + 1;
        float2 v0 = upk(acc[rp][0]), v1 = upk(acc[rp][1]);
        float2 v2 = upk(acc[rp][2]), v3 = upk(acc[rp][3]);
        uint2 h0; h0.x = packh2(v0.x, v1.x); h0.y = packh2(v2.x, v3.x);
        uint2 h1; h1.x = packh2(v0.y, v1.y); h1.y = packh2(v2.y, v3.y);
        *(uint2*)(g_gated + r0*128 + tc*4) = h0;
        *(uint2*)(g_gated + r1*128 + tc*4) = h1;
        ps[0] += v0.x + v0.y;  pq[0] += v0.x*v0.x + v0.y*v0.y;
        ps[1] += v1.x + v1.y;  pq[1] += v1.x*v1.x + v1.y*v1.y;
        ps[2] += v2.x + v2.y;  pq[2] += v2.x*v2.x + v2.y*v2.y;
        ps[3] += v3.x + v3.y;  pq[3] += v3.x*v3.x + v3.y*v3.y;
    }
#pragma unroll
    for (int j = 0; j < 4; j++) {
        int o = tc + 32*j;                 // true channel index
        sSum[tr*128 + o] = ps[j];
        sSq [tr*128 + o] = pq[j];
    }
    __syncthreads();
    if (tid < 128) {
        float s = 0.f, q = 0.f;
#pragma unroll
        for (int t = 0; t < 8; t++) { s += sSum[t*128 + tid]; q += sSq[t*128 + tid]; }
        atomicAdd(&g_sum1[tid], (double)s);
        atomicAdd(&g_sq1 [tid], (double)q);
    }
}

// ---------------- K4: BN1 affine (derived per-block) + sig*softplus + sum over M + BN2 stats ----------------
__global__ __launch_bounds__(256) void k4_reduce(const float* __restrict__ gam1,
                                                 const float* __restrict__ bet1) {
    __shared__ __align__(16) float sScale[128], sShift[128];
    __shared__ double sS[64], sQ[64];
    int tid = threadIdx.x;
    if (tid < 128) {
        double mean = g_sum1[tid] / (double)NROWS;
        double var  = g_sq1[tid] / (double)NROWS - mean * mean;
        float scale = gam1[tid] * rsqrtf((float)var + 1e-5f);
        float shift = bet1[tid] - (float)mean * scale;
        int slot = (tid & 31) * 4 + (tid >> 5);
        sScale[slot] = scale;
        sShift[slot] = shift;
    }
    if (tid < 64) { sS[tid] = 0.0; sQ[tid] = 0.0; }
    __syncthreads();

    int l = tid & 31, w = tid >> 5;
    long n = (long)blockIdx.x * 8 + w;
    float4 sc = *(const float4*)(sScale + l*4);
    float4 sh = *(const float4*)(sShift + l*4);
    float s0 = 0.f, s1 = 0.f;
    const __half* base = g_gated + n * 12 * 128 + l * 4;
#pragma unroll
    for (int m = 0; m < 12; m++) {
        uint2 g = *(const uint2*)(base + (long)m*128);
        float2 f01 = unph2(g.x);           // (filter l, filter l+32) pre-BN
        float2 f23 = unph2(g.y);           // (core   l, core   l+32) pre-BN
        float a0 = fmaf(f01.x, sc.x, sh.x);
        float a1 = fmaf(f01.y, sc.y, sh.y);
        float a2 = fmaf(f23.x, sc.z, sh.z);
        float a3 = fmaf(f23.y, sc.w, sh.w);
        s0 += sigmoidf_(a0) * softplusf(a2);
        s1 += sigmoidf_(a1) * softplusf(a3);
    }
    g_s[n*64 + l]      = s0;
    g_s[n*64 + 32 + l] = s1;
    atomicAdd(&sS[l],      (double)s0);
    atomicAdd(&sQ[l],      (double)s0 * (double)s0);
    atomicAdd(&sS[l + 32], (double)s1);
    atomicAdd(&sQ[l + 32], (double)s1 * (double)s1);
    __syncthreads();
    if (tid < 64) {
        atomicAdd(&g_sum2[tid], sS[tid]);
        atomicAdd(&g_sq2 [tid], sQ[tid]);
    }
}

// ---------------- K5: out = softplus(atom + BN2(nbr_sumed)), affine derived per-block ----------------
__global__ __launch_bounds__(256) void k5_out(const float* __restrict__ atom,
                                              const float* __restrict__ gam2,
                                              const float* __restrict__ bet2,
                                              float* __restrict__ out) {
    __shared__ float sSc[64], sSh[64];
    int tid = threadIdx.x;
    if (tid < 64) {
        double mean = g_sum2[tid] / (double)NA;
        double var  = g_sq2[tid] / (double)NA - mean * mean;
        float scale = gam2[tid] * rsqrtf((float)var + 1e-5f);
        sSc[tid] = scale;
        sSh[tid] = bet2[tid] - (float)mean * scale;
    }
    __syncthreads();
    int i = blockIdx.x * 256 + tid;             // one float4 group per thread
    int c4 = (i & 15) * 4;
    float4 a  = ((const float4*)atom)[i];
    float4 sv = ((const float4*)g_s)[i];
    float4 r;
    r.x = softplusf(a.x + fmaf(sv.x, sSc[c4+0], sSh[c4+0]));
    r.y = softplusf(a.y + fmaf(sv.y, sSc[c4+1], sSh[c4+1]));
    r.z = softplusf(a.z + fmaf(sv.z, sSc[c4+2], sSh[c4+2]));
    r.w = softplusf(a.w + fmaf(sv.w, sSc[c4+3], sSh[c4+3]));
    ((float4*)out)[i] = r;
}

// ---------------- launch ----------------
extern "C" void kernel_launch(void* const* d_in, const int* in_sizes, int n_in,
                              void* d_out, int out_size) {
    const float* atom = (const float*)d_in[0];   // [100000,64]
    const float* nbr  = (const float*)d_in[1];   // [100000,12,41]
    const int*   idxv = (const int*)  d_in[2];   // [100000,12]
    const float* fcw  = (const float*)d_in[3];   // [128,169]
    // d_in[4] = fc_b : cancels under BN1, unused
    const float* g1   = (const float*)d_in[5];
    const float* b1   = (const float*)d_in[6];
    const float* g2   = (const float*)d_in[7];
    const float* b2   = (const float*)d_in[8];
    float* out = (float*)d_out;

    cudaFuncSetAttribute(k1_proj,  cudaFuncAttributeMaxDynamicSharedMemorySize, SMEM_K1);
    cudaFuncSetAttribute(k2_gated, cudaFuncAttributeMaxDynamicSharedMemorySize, SMEM_K2);

    k0_zero<<<1, 128>>>();
    dim3 gk1((NA + 127) / 128, 2);
    k1_proj  <<<gk1, 256, SMEM_K1>>>(atom, fcw);
    k2_gated <<<NROWS / 128, 256, SMEM_K2>>>(nbr, idxv, fcw);
    k4_reduce<<<NA / 8, 256>>>(g1, b1);
    k5_out   <<<(NA * 64 / 4) / 256, 256>>>(atom, g2, b2, out);
}